// round 11
// baseline (speedup 1.0000x reference)
#include <cuda_runtime.h>
#include <cstdint>
#include <cstddef>

// Problem constants (fixed by the dataset)
#define N_PTS 32768
#define M_PTS 8192          // N * 0.25
#define CIN   64
#define COUT  128
#define KK    16

// ---------------- FPS config ----------------
#define FPS_CTAS 8
#define FPS_T    512
#define PPC (N_PTS / FPS_CTAS)   // 4096 points per CTA
#define PPT (PPC / FPS_T)        // 8 points per thread
#define NPAIR (PPT / 2)          // 4 packed f32x2 pairs
#define NWARPS (FPS_T / 32)      // 16

// FPS shared memory layout (bytes)
#define SM_POS   0                          // float4[4096] = 65536
#define SM_WRED  65536                      // u64[16]      = 128
#define SM_SLOT  65664                      // 2 parities x 8 ranks x 32B = 512
#define SM_WIN   66176                      // float[4] winner broadcast
#define FPS_SMEM 66304

#define XP 68                               // padded stride for MLP x-transpose tile
#define MLP_SMEM (64 * XP * 4 + CIN * COUT * 4)   // 17408 + 32768 = 50176

#define NCHUNK   8
#define KNN_TILE 2048

// Slot layout (32B): [0]=val_bits [4]=~idx [8]=x_bits [12]=y_bits
//                    [16]=flag(=round s) [20]=z_bits [24..31] pad
// (z,flag) written as ONE st.release.cluster.b64: seeing flag==s via
// ld.acquire.cluster guarantees the v4 payload is visible to that lane.
// NO cluster-scope fences anywhere in the loop (they emit CCTL.IVALL).

// ---------------- device scratch (no allocations allowed) ----------------
__device__ float4 g_pos4[N_PTS];
__device__ float4 g_sub4[M_PTS];
__device__ int    g_fps_idx[M_PTS];
__device__ float4 g_h4[N_PTS * (COUT / 4)];                 // 16 MB: relu(xW+b)
__device__ float  g_cand_d[(size_t)M_PTS * NCHUNK * KK];
__device__ int    g_cand_i[(size_t)M_PTS * NCHUNK * KK];
__device__ int    g_nbr[M_PTS * KK];

// ---------------- small PTX helpers ----------------
__device__ __forceinline__ unsigned s2u(const void* p) {
    return (unsigned)__cvta_generic_to_shared(p);
}
__device__ __forceinline__ unsigned mapa_rank(unsigned a, unsigned r) {
    unsigned ret;
    asm("mapa.shared::cluster.u32 %0, %1, %2;" : "=r"(ret) : "r"(a), "r"(r));
    return ret;
}
__device__ __forceinline__ void cluster_barrier() {
    asm volatile("barrier.cluster.arrive.aligned;" ::: "memory");
    asm volatile("barrier.cluster.wait.aligned;" ::: "memory");
}
__device__ __forceinline__ unsigned ctarank() {
    unsigned r;
    asm("mov.u32 %0, %%cluster_ctarank;" : "=r"(r));
    return r;
}
// Named barriers (producer/consumer split; standard CUTLASS pattern).
#define BAR_ARRIVE(id) \
    asm volatile("bar.arrive %0, %1;" :: "r"(id), "r"(FPS_T) : "memory")
#define BAR_SYNC(id) \
    asm volatile("bar.sync %0, %1;" :: "r"(id), "r"(FPS_T) : "memory")
// Packed f32x2: two independent IEEE-rn fp32 lanes per op (bit-identical to
// the scalar rn sequence; verified rel_err==0.0 across prior rounds).
#define PK2(out, lo, hi) \
    asm("mov.b64 %0, {%1, %2};" : "=l"(out) : "r"(lo), "r"(hi))
#define UPK2(lo, hi, in) \
    asm("mov.b64 {%0, %1}, %2;" : "=r"(lo), "=r"(hi) : "l"(in))
#define ADD2(out, a, b) \
    asm("add.rn.f32x2 %0, %1, %2;" : "=l"(out) : "l"(a), "l"(b))
#define MUL2(out, a, b) \
    asm("mul.rn.f32x2 %0, %1, %2;" : "=l"(out) : "l"(a), "l"(b))

// ---------------- pack pos -> float4 ----------------
__global__ void pack_kernel(const float* __restrict__ pos) {
    int i = blockIdx.x * 256 + threadIdx.x;
    if (i < N_PTS) {
        float4 v;
        v.x = pos[3 * i + 0];
        v.y = pos[3 * i + 1];
        v.z = pos[3 * i + 2];
        v.w = 0.0f;
        g_pos4[i] = v;
    }
}

// ---------------- FPS: 8-CTA cluster; packed f32x2 update; lazy argmax index;
// warp0-only DSMEM flag spin; asymmetric named barriers.
// Exactly replicates:  for s: d = sum((pos-pos[last])**2); mind = min(mind,d);
//                      next = argmax(mind)  (first-occurrence tie-break)
// d = add(add(mul(dx,dx),mul(dy,dy)),mul(dz,dz)) in rn, dx = px + (-lx) [== px-lx].
// Tie-break: key = (val_bits<<32) | ~global_idx, max -> lowest global idx on ties.
__global__ void __cluster_dims__(FPS_CTAS, 1, 1) fps_kernel(float* __restrict__ subpos_out) {
    extern __shared__ char smraw[];
    float4*             spos = (float4*)(smraw + SM_POS);
    unsigned long long* wred = (unsigned long long*)(smraw + SM_WRED);
    float*              swin = (float*)(smraw + SM_WIN);

    const unsigned rank = ctarank();
    const int tid  = threadIdx.x;
    const int lane = tid & 31;
    const int wid  = tid >> 5;
    const int gbase = (int)rank * PPC;

    // Init slot flags to a value no round uses (rounds are 1..M-1).
    if (tid < 16) {
        ((unsigned long long*)(smraw + SM_SLOT))[tid * 4 + 2] = 0xFFFFFFFFFFFFFFFFull;
    }

    // Load my slice into SMEM (winner-xyz lookup) and packed registers (compute).
    // Pair i holds points j=2i (lo lane) and j=2i+1 (hi lane);
    // global idx of point j = gbase + tid + j*FPS_T (ascending in j).
    unsigned long long px2[NPAIR], py2[NPAIR], pz2[NPAIR];
    float md[PPT];
    #pragma unroll
    for (int i = 0; i < NPAIR; ++i) {
        float4 a = g_pos4[gbase + tid + (2 * i) * FPS_T];
        float4 b = g_pos4[gbase + tid + (2 * i + 1) * FPS_T];
        spos[tid + (2 * i) * FPS_T]     = a;
        spos[tid + (2 * i + 1) * FPS_T] = b;
        PK2(px2[i], __float_as_uint(a.x), __float_as_uint(b.x));
        PK2(py2[i], __float_as_uint(a.y), __float_as_uint(b.y));
        PK2(pz2[i], __float_as_uint(a.z), __float_as_uint(b.z));
        md[2 * i]     = __int_as_float(0x7f800000);   // +inf
        md[2 * i + 1] = __int_as_float(0x7f800000);
    }
    float4 p0 = g_pos4[0];
    if (rank == 0 && tid == 0) {
        g_fps_idx[0]  = 0;
        subpos_out[0] = p0.x;
        subpos_out[1] = p0.y;
        subpos_out[2] = p0.z;
        g_sub4[0] = make_float4(p0.x, p0.y, p0.z, 0.0f);
    }
    __syncthreads();
    cluster_barrier();   // all slot flags initialized before any remote store

    float lx = p0.x, ly = p0.y, lz = p0.z;

    for (int s = 1; s < M_PTS; ++s) {
        const int par = s & 1;
        // ---- packed min-dist update; value-only max (no index bookkeeping)
        unsigned long long nlx2, nly2, nlz2;
        {
            unsigned nx = __float_as_uint(lx) ^ 0x80000000u;
            unsigned ny = __float_as_uint(ly) ^ 0x80000000u;
            unsigned nz = __float_as_uint(lz) ^ 0x80000000u;
            PK2(nlx2, nx, nx); PK2(nly2, ny, ny); PK2(nlz2, nz, nz);
        }
        float bv = -1.0f;
        #pragma unroll
        for (int i = 0; i < NPAIR; ++i) {
            unsigned long long dx2, dy2, dz2, xx2, yy2, zz2, s2, d2;
            ADD2(dx2, px2[i], nlx2);      // px - lx (exact: a + (-b))
            ADD2(dy2, py2[i], nly2);
            ADD2(dz2, pz2[i], nlz2);
            MUL2(xx2, dx2, dx2);
            MUL2(yy2, dy2, dy2);
            MUL2(zz2, dz2, dz2);
            ADD2(s2, xx2, yy2);
            ADD2(d2, s2, zz2);
            unsigned u0, u1;
            UPK2(u0, u1, d2);
            float m0 = fminf(md[2 * i], __uint_as_float(u0));
            md[2 * i] = m0;
            float m1 = fminf(md[2 * i + 1], __uint_as_float(u1));
            md[2 * i + 1] = m1;
            bv = fmaxf(bv, fmaxf(m0, m1));   // value-exact: max over positives
        }
        // ---- warp argmax via redux (bv >= 0 so uint order == float order)
        unsigned vb   = __float_as_uint(bv);
        unsigned wmax = __reduce_max_sync(0xFFFFFFFFu, vb);
        unsigned binv = 0;
        if (vb == wmax) {
            // lazy index: smallest j with md[j]==bv (bit-exact: fmaxf returns
            // one operand) -> lowest global idx, matching first-max semantics
            int bj = 0;
            #pragma unroll
            for (int j = PPT - 1; j >= 0; --j)
                if (md[j] == bv) bj = j;
            binv = ~(unsigned)(gbase + tid + bj * FPS_T);
        }
        unsigned imax = __reduce_max_sync(0xFFFFFFFFu, binv);
        if (lane == 0)
            wred[wid] = ((unsigned long long)wmax << 32) | imax;

        // ---- asymmetric barriers: producers arrive bar1; warp0 syncs bar1
        if (wid == 0) {
            BAR_SYNC(1);   // all wred[] writes visible (bar drains STS)

            unsigned long long k = (lane < NWARPS) ? wred[lane] : 0ull;
            unsigned v2 = (unsigned)(k >> 32);
            unsigned m2 = __reduce_max_sync(0xFFFFFFFFu, v2);
            unsigned i2c = (v2 == m2) ? (unsigned)k : 0u;
            unsigned i2 = __reduce_max_sync(0xFFFFFFFFu, i2c);
            unsigned gi = ~i2;
            int li = (int)gi - gbase;
            float4 c = spos[li];              // broadcast LDS, all lanes same addr

            const char* sb = smraw + SM_SLOT + par * (FPS_CTAS * 32);
            unsigned long long mykey = 0;
            float sx = 0.f, sy = 0.f, sz = 0.f;
            if (lane < FPS_CTAS) {
                // post my CTA's candidate into slot[rank] of CTA 'lane'
                unsigned a = mapa_rank(s2u(sb + (int)rank * 32), (unsigned)lane);
                asm volatile("st.shared::cluster.v4.b32 [%0], {%1,%2,%3,%4};"
                             :: "r"(a), "r"(m2), "r"(i2),
                                "r"(__float_as_uint(c.x)), "r"(__float_as_uint(c.y))
                             : "memory");
                unsigned long long zf =
                    ((unsigned long long)__float_as_uint(c.z) << 32) | (unsigned)s;
                asm volatile("st.release.cluster.shared::cluster.b64 [%0], %1;"
                             :: "r"(a + 16), "l"(zf) : "memory");

                // spin on MY local flag (slot[lane]) until round s posted
                unsigned fa = s2u(sb + lane * 32 + 16);
                unsigned long long zfl;
                do {
                    asm volatile("ld.acquire.cluster.shared::cta.b64 %0, [%1];"
                                 : "=l"(zfl) : "r"(fa) : "memory");
                } while ((unsigned)zfl != (unsigned)s);
                uint4 v = *(const uint4*)(sb + lane * 32);  // ordered by my acquire
                mykey = ((unsigned long long)v.x << 32) | v.y;
                sx = __uint_as_float(v.z);
                sy = __uint_as_float(v.w);
                sz = __uint_as_float((unsigned)(zfl >> 32));
            }
            // winner across the 8 lane-held candidates
            unsigned v3 = (unsigned)(mykey >> 32);
            unsigned m3 = __reduce_max_sync(0xFFFFFFFFu, v3);
            unsigned i3c = (v3 == m3 && lane < FPS_CTAS) ? (unsigned)mykey : 0u;
            unsigned i3 = __reduce_max_sync(0xFFFFFFFFu, i3c);
            unsigned long long wkey = ((unsigned long long)m3 << 32) | i3;
            if (lane < FPS_CTAS && mykey == wkey) {
                swin[0] = sx;
                swin[1] = sy;
                swin[2] = sz;
                if (rank == 0) {
                    unsigned wg = ~i3;
                    g_fps_idx[s] = (int)wg;
                    subpos_out[3 * s + 0] = sx;
                    subpos_out[3 * s + 1] = sy;
                    subpos_out[3 * s + 2] = sz;
                    g_sub4[s] = make_float4(sx, sy, sz, 0.0f);
                }
            }
            __syncwarp();                 // winner's swin STS visible to warp0
            lx = swin[0];
            ly = swin[1];
            lz = swin[2];
            BAR_ARRIVE(2);                // release warps 1..15; no blocking
        } else {
            BAR_ARRIVE(1);                // non-blocking; wred already posted
            BAR_SYNC(2);                  // wait for winner; orders swin reads
            lx = swin[0];
            ly = swin[1];
            lz = swin[2];
        }
    }
}

// ---------------- MLP: h = relu(x @ W + b), fp32 ----------------
__global__ void mlp_kernel(const float* __restrict__ x,
                           const float* __restrict__ W,
                           const float* __restrict__ bias) {
    extern __shared__ float sm[];
    float* sX = sm;                 // [CIN][XP]  (k-major, padded)
    float* sW = sm + 64 * XP;       // [CIN][COUT]
    int rBase = blockIdx.x * 64;

    for (int i = threadIdx.x; i < (CIN * COUT) / 4; i += 256)
        ((float4*)sW)[i] = ((const float4*)W)[i];
    for (int i = threadIdx.x; i < 1024; i += 256) {
        int r  = i >> 4;
        int k4 = (i & 15) << 2;
        float4 v = ((const float4*)(x + (size_t)(rBase + r) * CIN))[i & 15];
        sX[(k4 + 0) * XP + r] = v.x;
        sX[(k4 + 1) * XP + r] = v.y;
        sX[(k4 + 2) * XP + r] = v.z;
        sX[(k4 + 3) * XP + r] = v.w;
    }
    __syncthreads();

    int ty = threadIdx.x >> 4, tx = threadIdx.x & 15;
    int r0 = ty * 4, c0 = tx * 8;
    float acc[4][8];
    #pragma unroll
    for (int i = 0; i < 4; ++i)
        #pragma unroll
        for (int j = 0; j < 8; ++j) acc[i][j] = 0.0f;

    #pragma unroll 4
    for (int k = 0; k < CIN; ++k) {
        float4 xr = *(const float4*)&sX[k * XP + r0];
        float4 wa = *(const float4*)&sW[k * COUT + c0];
        float4 wb = *(const float4*)&sW[k * COUT + c0 + 4];
        float xv[4] = {xr.x, xr.y, xr.z, xr.w};
        float wv[8] = {wa.x, wa.y, wa.z, wa.w, wb.x, wb.y, wb.z, wb.w};
        #pragma unroll
        for (int i = 0; i < 4; ++i)
            #pragma unroll
            for (int j = 0; j < 8; ++j)
                acc[i][j] = fmaf(xv[i], wv[j], acc[i][j]);
    }
    #pragma unroll
    for (int i = 0; i < 4; ++i) {
        int row = rBase + r0 + i;
        float4 o1, o2;
        o1.x = fmaxf(acc[i][0] + bias[c0 + 0], 0.0f);
        o1.y = fmaxf(acc[i][1] + bias[c0 + 1], 0.0f);
        o1.z = fmaxf(acc[i][2] + bias[c0 + 2], 0.0f);
        o1.w = fmaxf(acc[i][3] + bias[c0 + 3], 0.0f);
        o2.x = fmaxf(acc[i][4] + bias[c0 + 4], 0.0f);
        o2.y = fmaxf(acc[i][5] + bias[c0 + 5], 0.0f);
        o2.z = fmaxf(acc[i][6] + bias[c0 + 6], 0.0f);
        o2.w = fmaxf(acc[i][7] + bias[c0 + 7], 0.0f);
        g_h4[(size_t)row * (COUT / 4) + (c0 >> 2) + 0] = o1;
        g_h4[(size_t)row * (COUT / 4) + (c0 >> 2) + 1] = o2;
    }
}

// ---------------- KNN phase 1: per-(query,chunk) top-16 ----------------
__global__ void knn_kernel() {
    __shared__ float4 tile[KNN_TILE];
    int q     = blockIdx.x * 256 + threadIdx.x;    // 0..M-1
    int chunk = blockIdx.y;
    int base  = chunk * (N_PTS / NCHUNK);

    float4 qp = g_sub4[q];
    float bd[KK];
    int   bi[KK];
    #pragma unroll
    for (int k = 0; k < KK; ++k) { bd[k] = __int_as_float(0x7f800000); bi[k] = 0; }

    for (int t = 0; t < (N_PTS / NCHUNK) / KNN_TILE; ++t) {
        for (int i = threadIdx.x; i < KNN_TILE; i += 256)
            tile[i] = g_pos4[base + t * KNN_TILE + i];
        __syncthreads();
        int nb = base + t * KNN_TILE;
        for (int i = 0; i < KNN_TILE; ++i) {
            float4 p = tile[i];
            float dx = __fsub_rn(qp.x, p.x);
            float dy = __fsub_rn(qp.y, p.y);
            float dz = __fsub_rn(qp.z, p.z);
            float d  = __fadd_rn(__fadd_rn(__fmul_rn(dx, dx), __fmul_rn(dy, dy)),
                                 __fmul_rn(dz, dz));
            if (d < bd[KK - 1]) {           // strict <: stable (earlier index wins ties)
                bd[KK - 1] = d;
                bi[KK - 1] = nb + i;
                #pragma unroll
                for (int j = KK - 1; j > 0; --j) {
                    if (bd[j] < bd[j - 1]) {
                        float td = bd[j]; bd[j] = bd[j - 1]; bd[j - 1] = td;
                        int   ti = bi[j]; bi[j] = bi[j - 1]; bi[j - 1] = ti;
                    }
                }
            }
        }
        __syncthreads();
    }
    size_t o = ((size_t)q * NCHUNK + chunk) * KK;
    #pragma unroll
    for (int k = 0; k < KK; ++k) {
        g_cand_d[o + k] = bd[k];
        g_cand_i[o + k] = bi[k];
    }
}

// ---------------- KNN phase 2: merge 8 sorted lists + sub_batch ----------------
__global__ void merge_kernel(const int* __restrict__ batch, float* __restrict__ d_out) {
    int q = blockIdx.x * 256 + threadIdx.x;
    if (q >= M_PTS) return;
    int head[NCHUNK];
    unsigned long long hk[NCHUNK];
    #pragma unroll
    for (int c = 0; c < NCHUNK; ++c) {
        head[c] = 0;
        size_t o = ((size_t)q * NCHUNK + c) * KK;
        hk[c] = ((unsigned long long)__float_as_uint(g_cand_d[o]) << 32) |
                (unsigned)g_cand_i[o];
    }
    #pragma unroll
    for (int k = 0; k < KK; ++k) {
        int cb = 0;
        unsigned long long bk = hk[0];
        #pragma unroll
        for (int c = 1; c < NCHUNK; ++c)
            if (hk[c] < bk) { bk = hk[c]; cb = c; }
        g_nbr[q * KK + k] = (int)(bk & 0xFFFFFFFFull);
        int h = ++head[cb];
        if (h < KK) {
            size_t o = ((size_t)q * NCHUNK + cb) * KK + h;
            hk[cb] = ((unsigned long long)__float_as_uint(g_cand_d[o]) << 32) |
                     (unsigned)g_cand_i[o];
        } else {
            hk[cb] = 0xFFFFFFFFFFFFFFFFull;
        }
    }
    d_out[(size_t)M_PTS * COUT + (size_t)M_PTS * 3 + q] = (float)batch[g_fps_idx[q]];
}

// ---------------- gather + max over K neighbors ----------------
__global__ void gather_max_kernel(float* __restrict__ d_out) {
    int gw   = (blockIdx.x * blockDim.x + threadIdx.x) >> 5;   // query id
    int lane = threadIdx.x & 31;
    float4 acc = make_float4(-__int_as_float(0x7f800000),
                             -__int_as_float(0x7f800000),
                             -__int_as_float(0x7f800000),
                             -__int_as_float(0x7f800000));
    #pragma unroll
    for (int k = 0; k < KK; ++k) {
        int n = g_nbr[gw * KK + k];
        float4 v = g_h4[(size_t)n * (COUT / 4) + lane];
        acc.x = fmaxf(acc.x, v.x);
        acc.y = fmaxf(acc.y, v.y);
        acc.z = fmaxf(acc.z, v.z);
        acc.w = fmaxf(acc.w, v.w);
    }
    ((float4*)d_out)[(size_t)gw * (COUT / 4) + lane] = acc;
}

// ---------------- launch ----------------
extern "C" void kernel_launch(void* const* d_in, const int* in_sizes, int n_in,
                              void* d_out, int out_size) {
    const float* x     = (const float*)d_in[0];
    const float* pos   = (const float*)d_in[1];
    const int*   batch = (const int*)  d_in[2];
    const float* W     = (const float*)d_in[3];
    const float* b     = (const float*)d_in[4];
    float* out = (float*)d_out;
    (void)in_sizes; (void)n_in; (void)out_size;

    cudaFuncSetAttribute(fps_kernel, cudaFuncAttributeMaxDynamicSharedMemorySize, FPS_SMEM);
    cudaFuncSetAttribute(mlp_kernel, cudaFuncAttributeMaxDynamicSharedMemorySize, MLP_SMEM);

    pack_kernel<<<(N_PTS + 255) / 256, 256>>>(pos);
    mlp_kernel<<<N_PTS / 64, 256, MLP_SMEM>>>(x, W, b);
    fps_kernel<<<FPS_CTAS, FPS_T, FPS_SMEM>>>(out + (size_t)M_PTS * COUT);
    knn_kernel<<<dim3(M_PTS / 256, NCHUNK), 256>>>();
    merge_kernel<<<M_PTS / 256, 256>>>(batch, out);
    gather_max_kernel<<<M_PTS / 8, 256>>>(out);
}

// round 12
// speedup vs baseline: 1.1143x; 1.1143x over previous
#include <cuda_runtime.h>
#include <cstdint>
#include <cstddef>

// Problem constants (fixed by the dataset)
#define N_PTS 32768
#define M_PTS 8192          // N * 0.25
#define CIN   64
#define COUT  128
#define KK    16

// ---------------- FPS config ----------------
#define FPS_CTAS 8
#define FPS_T    512
#define PPC (N_PTS / FPS_CTAS)   // 4096 points per CTA
#define PPT (PPC / FPS_T)        // 8 points per thread
#define NPAIR (PPT / 2)          // 4 packed f32x2 pairs
#define NWARPS (FPS_T / 32)      // 16

// FPS shared memory layout (bytes)
#define SM_POS   0                          // float4[4096] = 65536
#define SM_WRED  65536                      // u64[16]      = 128
#define SM_SLOT  65664                      // 2 parities x 8 ranks x 32B = 512
#define SM_WIN   66176                      // float[4] winner broadcast
#define FPS_SMEM 66304

#define XP 68                               // padded stride for MLP x-transpose tile
#define MLP_SMEM (64 * XP * 4 + CIN * COUT * 4)   // 17408 + 32768 = 50176

#define NCHUNK   8
#define KNN_TILE 2048

// Slot layout (32B): [0]=val_bits [4]=~idx [8]=x_bits [12]=y_bits
//                    [16]=flag(=round s) [20]=z_bits [24..31] pad
// (z,flag) written as ONE st.release.cluster.b64: seeing flag==s via
// ld.acquire.cluster guarantees the v4 payload is visible to that lane.
// NO cluster-scope fences anywhere in the loop (they emit CCTL.IVALL).

// ---------------- device scratch (no allocations allowed) ----------------
__device__ float4 g_pos4[N_PTS];
__device__ float4 g_sub4[M_PTS];
__device__ int    g_fps_idx[M_PTS];
__device__ float4 g_h4[N_PTS * (COUT / 4)];                 // 16 MB: relu(xW+b)
__device__ float  g_cand_d[(size_t)M_PTS * NCHUNK * KK];
__device__ int    g_cand_i[(size_t)M_PTS * NCHUNK * KK];
__device__ int    g_nbr[M_PTS * KK];

// ---------------- small PTX helpers ----------------
__device__ __forceinline__ unsigned s2u(const void* p) {
    return (unsigned)__cvta_generic_to_shared(p);
}
__device__ __forceinline__ unsigned mapa_rank(unsigned a, unsigned r) {
    unsigned ret;
    asm("mapa.shared::cluster.u32 %0, %1, %2;" : "=r"(ret) : "r"(a), "r"(r));
    return ret;
}
__device__ __forceinline__ void cluster_barrier() {
    asm volatile("barrier.cluster.arrive.aligned;" ::: "memory");
    asm volatile("barrier.cluster.wait.aligned;" ::: "memory");
}
__device__ __forceinline__ unsigned ctarank() {
    unsigned r;
    asm("mov.u32 %0, %%cluster_ctarank;" : "=r"(r));
    return r;
}
// Packed f32x2: two independent IEEE-rn fp32 lanes per op (bit-identical to
// the scalar rn sequence; verified rel_err==0.0 across prior rounds).
#define PK2(out, lo, hi) \
    asm("mov.b64 %0, {%1, %2};" : "=l"(out) : "r"(lo), "r"(hi))
#define UPK2(lo, hi, in) \
    asm("mov.b64 {%0, %1}, %2;" : "=r"(lo), "=r"(hi) : "l"(in))
#define ADD2(out, a, b) \
    asm("add.rn.f32x2 %0, %1, %2;" : "=l"(out) : "l"(a), "l"(b))
#define MUL2(out, a, b) \
    asm("mul.rn.f32x2 %0, %1, %2;" : "=l"(out) : "l"(a), "l"(b))

// ---------------- pack pos -> float4 ----------------
__global__ void pack_kernel(const float* __restrict__ pos) {
    int i = blockIdx.x * 256 + threadIdx.x;
    if (i < N_PTS) {
        float4 v;
        v.x = pos[3 * i + 0];
        v.y = pos[3 * i + 1];
        v.z = pos[3 * i + 2];
        v.w = 0.0f;
        g_pos4[i] = v;
    }
}

// ---------------- FPS: 8-CTA cluster; packed f32x2 update; lazy argmax index;
// warp0-only DSMEM flag spin; plain __syncthreads fabric (R10 structure).
// Exactly replicates:  for s: d = sum((pos-pos[last])**2); mind = min(mind,d);
//                      next = argmax(mind)  (first-occurrence tie-break)
// d = add(add(mul(dx,dx),mul(dy,dy)),mul(dz,dz)) in rn, dx = px + (-lx) [== px-lx].
// Tie-break: key = (val_bits<<32) | ~global_idx, max -> lowest global idx on ties.
__global__ void __cluster_dims__(FPS_CTAS, 1, 1) fps_kernel(float* __restrict__ subpos_out) {
    extern __shared__ char smraw[];
    float4*             spos = (float4*)(smraw + SM_POS);
    unsigned long long* wred = (unsigned long long*)(smraw + SM_WRED);
    float*              swin = (float*)(smraw + SM_WIN);

    const unsigned rank = ctarank();
    const int tid  = threadIdx.x;
    const int lane = tid & 31;
    const int wid  = tid >> 5;
    const int gbase = (int)rank * PPC;

    // Init slot flags to a value no round uses (rounds are 1..M-1).
    if (tid < 16) {
        ((unsigned long long*)(smraw + SM_SLOT))[tid * 4 + 2] = 0xFFFFFFFFFFFFFFFFull;
    }

    // Load my slice into SMEM (winner-xyz lookup) and packed registers (compute).
    // Pair i holds points j=2i (lo lane) and j=2i+1 (hi lane);
    // global idx of point j = gbase + tid + j*FPS_T (ascending in j).
    unsigned long long px2[NPAIR], py2[NPAIR], pz2[NPAIR];
    float md[PPT];
    #pragma unroll
    for (int i = 0; i < NPAIR; ++i) {
        float4 a = g_pos4[gbase + tid + (2 * i) * FPS_T];
        float4 b = g_pos4[gbase + tid + (2 * i + 1) * FPS_T];
        spos[tid + (2 * i) * FPS_T]     = a;
        spos[tid + (2 * i + 1) * FPS_T] = b;
        PK2(px2[i], __float_as_uint(a.x), __float_as_uint(b.x));
        PK2(py2[i], __float_as_uint(a.y), __float_as_uint(b.y));
        PK2(pz2[i], __float_as_uint(a.z), __float_as_uint(b.z));
        md[2 * i]     = __int_as_float(0x7f800000);   // +inf
        md[2 * i + 1] = __int_as_float(0x7f800000);
    }
    float4 p0 = g_pos4[0];
    if (rank == 0 && tid == 0) {
        g_fps_idx[0]  = 0;
        subpos_out[0] = p0.x;
        subpos_out[1] = p0.y;
        subpos_out[2] = p0.z;
        g_sub4[0] = make_float4(p0.x, p0.y, p0.z, 0.0f);
    }
    __syncthreads();
    cluster_barrier();   // all slot flags initialized before any remote store

    float lx = p0.x, ly = p0.y, lz = p0.z;

    for (int s = 1; s < M_PTS; ++s) {
        const int par = s & 1;
        // ---- packed min-dist update; value-only max (no index bookkeeping)
        unsigned long long nlx2, nly2, nlz2;
        {
            unsigned nx = __float_as_uint(lx) ^ 0x80000000u;
            unsigned ny = __float_as_uint(ly) ^ 0x80000000u;
            unsigned nz = __float_as_uint(lz) ^ 0x80000000u;
            PK2(nlx2, nx, nx); PK2(nly2, ny, ny); PK2(nlz2, nz, nz);
        }
        float bv = -1.0f;
        #pragma unroll
        for (int i = 0; i < NPAIR; ++i) {
            unsigned long long dx2, dy2, dz2, xx2, yy2, zz2, s2, d2;
            ADD2(dx2, px2[i], nlx2);      // px - lx (exact: a + (-b))
            ADD2(dy2, py2[i], nly2);
            ADD2(dz2, pz2[i], nlz2);
            MUL2(xx2, dx2, dx2);
            MUL2(yy2, dy2, dy2);
            MUL2(zz2, dz2, dz2);
            ADD2(s2, xx2, yy2);
            ADD2(d2, s2, zz2);
            unsigned u0, u1;
            UPK2(u0, u1, d2);
            float m0 = fminf(md[2 * i], __uint_as_float(u0));
            md[2 * i] = m0;
            float m1 = fminf(md[2 * i + 1], __uint_as_float(u1));
            md[2 * i + 1] = m1;
            bv = fmaxf(bv, fmaxf(m0, m1));   // value-exact: max over positives
        }
        // ---- warp argmax via redux (bv >= 0 so uint order == float order)
        unsigned vb   = __float_as_uint(bv);
        unsigned wmax = __reduce_max_sync(0xFFFFFFFFu, vb);
        unsigned binv = 0;
        if (vb == wmax) {
            // lazy index: smallest j with md[j]==bv (bit-exact: fmaxf returns
            // one operand) -> lowest global idx, matching first-max semantics
            int bj = 0;
            #pragma unroll
            for (int j = PPT - 1; j >= 0; --j)
                if (md[j] == bv) bj = j;
            binv = ~(unsigned)(gbase + tid + bj * FPS_T);
        }
        unsigned imax = __reduce_max_sync(0xFFFFFFFFu, binv);
        if (lane == 0)
            wred[wid] = ((unsigned long long)wmax << 32) | imax;
        __syncthreads();

        // ---- warp 0: block argmax, candidate broadcast, flag spin, winner pick
        if (wid == 0) {
            unsigned long long k = (lane < NWARPS) ? wred[lane] : 0ull;
            unsigned v2 = (unsigned)(k >> 32);
            unsigned m2 = __reduce_max_sync(0xFFFFFFFFu, v2);
            unsigned i2c = (v2 == m2) ? (unsigned)k : 0u;
            unsigned i2 = __reduce_max_sync(0xFFFFFFFFu, i2c);
            unsigned gi = ~i2;
            int li = (int)gi - gbase;
            float4 c = spos[li];              // broadcast LDS, all lanes same addr

            const char* sb = smraw + SM_SLOT + par * (FPS_CTAS * 32);
            unsigned long long mykey = 0;
            float sx = 0.f, sy = 0.f, sz = 0.f;
            if (lane < FPS_CTAS) {
                // post my CTA's candidate into slot[rank] of CTA 'lane'
                unsigned a = mapa_rank(s2u(sb + (int)rank * 32), (unsigned)lane);
                asm volatile("st.shared::cluster.v4.b32 [%0], {%1,%2,%3,%4};"
                             :: "r"(a), "r"(m2), "r"(i2),
                                "r"(__float_as_uint(c.x)), "r"(__float_as_uint(c.y))
                             : "memory");
                unsigned long long zf =
                    ((unsigned long long)__float_as_uint(c.z) << 32) | (unsigned)s;
                asm volatile("st.release.cluster.shared::cluster.b64 [%0], %1;"
                             :: "r"(a + 16), "l"(zf) : "memory");

                // spin on MY local flag (slot[lane]) until round s posted
                unsigned fa = s2u(sb + lane * 32 + 16);
                unsigned long long zfl;
                do {
                    asm volatile("ld.acquire.cluster.shared::cta.b64 %0, [%1];"
                                 : "=l"(zfl) : "r"(fa) : "memory");
                } while ((unsigned)zfl != (unsigned)s);
                uint4 v = *(const uint4*)(sb + lane * 32);  // ordered by my acquire
                mykey = ((unsigned long long)v.x << 32) | v.y;
                sx = __uint_as_float(v.z);
                sy = __uint_as_float(v.w);
                sz = __uint_as_float((unsigned)(zfl >> 32));
            }
            // winner across the 8 lane-held candidates
            unsigned v3 = (unsigned)(mykey >> 32);
            unsigned m3 = __reduce_max_sync(0xFFFFFFFFu, v3);
            unsigned i3c = (v3 == m3 && lane < FPS_CTAS) ? (unsigned)mykey : 0u;
            unsigned i3 = __reduce_max_sync(0xFFFFFFFFu, i3c);
            unsigned long long wkey = ((unsigned long long)m3 << 32) | i3;
            if (lane < FPS_CTAS && mykey == wkey) {
                swin[0] = sx;
                swin[1] = sy;
                swin[2] = sz;
                if (rank == 0) {
                    unsigned wg = ~i3;
                    g_fps_idx[s] = (int)wg;
                    subpos_out[3 * s + 0] = sx;
                    subpos_out[3 * s + 1] = sy;
                    subpos_out[3 * s + 2] = sz;
                    g_sub4[s] = make_float4(sx, sy, sz, 0.0f);
                }
            }
        }
        __syncthreads();   // releases warps 1..15; orders swin for all
        lx = swin[0];
        ly = swin[1];
        lz = swin[2];
    }
}

// ---------------- MLP: h = relu(x @ W + b), fp32 ----------------
__global__ void mlp_kernel(const float* __restrict__ x,
                           const float* __restrict__ W,
                           const float* __restrict__ bias) {
    extern __shared__ float sm[];
    float* sX = sm;                 // [CIN][XP]  (k-major, padded)
    float* sW = sm + 64 * XP;       // [CIN][COUT]
    int rBase = blockIdx.x * 64;

    for (int i = threadIdx.x; i < (CIN * COUT) / 4; i += 256)
        ((float4*)sW)[i] = ((const float4*)W)[i];
    for (int i = threadIdx.x; i < 1024; i += 256) {
        int r  = i >> 4;
        int k4 = (i & 15) << 2;
        float4 v = ((const float4*)(x + (size_t)(rBase + r) * CIN))[i & 15];
        sX[(k4 + 0) * XP + r] = v.x;
        sX[(k4 + 1) * XP + r] = v.y;
        sX[(k4 + 2) * XP + r] = v.z;
        sX[(k4 + 3) * XP + r] = v.w;
    }
    __syncthreads();

    int ty = threadIdx.x >> 4, tx = threadIdx.x & 15;
    int r0 = ty * 4, c0 = tx * 8;
    float acc[4][8];
    #pragma unroll
    for (int i = 0; i < 4; ++i)
        #pragma unroll
        for (int j = 0; j < 8; ++j) acc[i][j] = 0.0f;

    #pragma unroll 4
    for (int k = 0; k < CIN; ++k) {
        float4 xr = *(const float4*)&sX[k * XP + r0];
        float4 wa = *(const float4*)&sW[k * COUT + c0];
        float4 wb = *(const float4*)&sW[k * COUT + c0 + 4];
        float xv[4] = {xr.x, xr.y, xr.z, xr.w};
        float wv[8] = {wa.x, wa.y, wa.z, wa.w, wb.x, wb.y, wb.z, wb.w};
        #pragma unroll
        for (int i = 0; i < 4; ++i)
            #pragma unroll
            for (int j = 0; j < 8; ++j)
                acc[i][j] = fmaf(xv[i], wv[j], acc[i][j]);
    }
    #pragma unroll
    for (int i = 0; i < 4; ++i) {
        int row = rBase + r0 + i;
        float4 o1, o2;
        o1.x = fmaxf(acc[i][0] + bias[c0 + 0], 0.0f);
        o1.y = fmaxf(acc[i][1] + bias[c0 + 1], 0.0f);
        o1.z = fmaxf(acc[i][2] + bias[c0 + 2], 0.0f);
        o1.w = fmaxf(acc[i][3] + bias[c0 + 3], 0.0f);
        o2.x = fmaxf(acc[i][4] + bias[c0 + 4], 0.0f);
        o2.y = fmaxf(acc[i][5] + bias[c0 + 5], 0.0f);
        o2.z = fmaxf(acc[i][6] + bias[c0 + 6], 0.0f);
        o2.w = fmaxf(acc[i][7] + bias[c0 + 7], 0.0f);
        g_h4[(size_t)row * (COUT / 4) + (c0 >> 2) + 0] = o1;
        g_h4[(size_t)row * (COUT / 4) + (c0 >> 2) + 1] = o2;
    }
}

// ---------------- KNN phase 1: per-(query,chunk) top-16 ----------------
__global__ void knn_kernel() {
    __shared__ float4 tile[KNN_TILE];
    int q     = blockIdx.x * 256 + threadIdx.x;    // 0..M-1
    int chunk = blockIdx.y;
    int base  = chunk * (N_PTS / NCHUNK);

    float4 qp = g_sub4[q];
    float bd[KK];
    int   bi[KK];
    #pragma unroll
    for (int k = 0; k < KK; ++k) { bd[k] = __int_as_float(0x7f800000); bi[k] = 0; }

    for (int t = 0; t < (N_PTS / NCHUNK) / KNN_TILE; ++t) {
        for (int i = threadIdx.x; i < KNN_TILE; i += 256)
            tile[i] = g_pos4[base + t * KNN_TILE + i];
        __syncthreads();
        int nb = base + t * KNN_TILE;
        for (int i = 0; i < KNN_TILE; ++i) {
            float4 p = tile[i];
            float dx = __fsub_rn(qp.x, p.x);
            float dy = __fsub_rn(qp.y, p.y);
            float dz = __fsub_rn(qp.z, p.z);
            float d  = __fadd_rn(__fadd_rn(__fmul_rn(dx, dx), __fmul_rn(dy, dy)),
                                 __fmul_rn(dz, dz));
            if (d < bd[KK - 1]) {           // strict <: stable (earlier index wins ties)
                bd[KK - 1] = d;
                bi[KK - 1] = nb + i;
                #pragma unroll
                for (int j = KK - 1; j > 0; --j) {
                    if (bd[j] < bd[j - 1]) {
                        float td = bd[j]; bd[j] = bd[j - 1]; bd[j - 1] = td;
                        int   ti = bi[j]; bi[j] = bi[j - 1]; bi[j - 1] = ti;
                    }
                }
            }
        }
        __syncthreads();
    }
    size_t o = ((size_t)q * NCHUNK + chunk) * KK;
    #pragma unroll
    for (int k = 0; k < KK; ++k) {
        g_cand_d[o + k] = bd[k];
        g_cand_i[o + k] = bi[k];
    }
}

// ---------------- KNN phase 2: merge 8 sorted lists + sub_batch ----------------
__global__ void merge_kernel(const int* __restrict__ batch, float* __restrict__ d_out) {
    int q = blockIdx.x * 256 + threadIdx.x;
    if (q >= M_PTS) return;
    int head[NCHUNK];
    unsigned long long hk[NCHUNK];
    #pragma unroll
    for (int c = 0; c < NCHUNK; ++c) {
        head[c] = 0;
        size_t o = ((size_t)q * NCHUNK + c) * KK;
        hk[c] = ((unsigned long long)__float_as_uint(g_cand_d[o]) << 32) |
                (unsigned)g_cand_i[o];
    }
    #pragma unroll
    for (int k = 0; k < KK; ++k) {
        int cb = 0;
        unsigned long long bk = hk[0];
        #pragma unroll
        for (int c = 1; c < NCHUNK; ++c)
            if (hk[c] < bk) { bk = hk[c]; cb = c; }
        g_nbr[q * KK + k] = (int)(bk & 0xFFFFFFFFull);
        int h = ++head[cb];
        if (h < KK) {
            size_t o = ((size_t)q * NCHUNK + cb) * KK + h;
            hk[cb] = ((unsigned long long)__float_as_uint(g_cand_d[o]) << 32) |
                     (unsigned)g_cand_i[o];
        } else {
            hk[cb] = 0xFFFFFFFFFFFFFFFFull;
        }
    }
    d_out[(size_t)M_PTS * COUT + (size_t)M_PTS * 3 + q] = (float)batch[g_fps_idx[q]];
}

// ---------------- gather + max over K neighbors ----------------
__global__ void gather_max_kernel(float* __restrict__ d_out) {
    int gw   = (blockIdx.x * blockDim.x + threadIdx.x) >> 5;   // query id
    int lane = threadIdx.x & 31;
    float4 acc = make_float4(-__int_as_float(0x7f800000),
                             -__int_as_float(0x7f800000),
                             -__int_as_float(0x7f800000),
                             -__int_as_float(0x7f800000));
    #pragma unroll
    for (int k = 0; k < KK; ++k) {
        int n = g_nbr[gw * KK + k];
        float4 v = g_h4[(size_t)n * (COUT / 4) + lane];
        acc.x = fmaxf(acc.x, v.x);
        acc.y = fmaxf(acc.y, v.y);
        acc.z = fmaxf(acc.z, v.z);
        acc.w = fmaxf(acc.w, v.w);
    }
    ((float4*)d_out)[(size_t)gw * (COUT / 4) + lane] = acc;
}

// ---------------- launch ----------------
extern "C" void kernel_launch(void* const* d_in, const int* in_sizes, int n_in,
                              void* d_out, int out_size) {
    const float* x     = (const float*)d_in[0];
    const float* pos   = (const float*)d_in[1];
    const int*   batch = (const int*)  d_in[2];
    const float* W     = (const float*)d_in[3];
    const float* b     = (const float*)d_in[4];
    float* out = (float*)d_out;
    (void)in_sizes; (void)n_in; (void)out_size;

    cudaFuncSetAttribute(fps_kernel, cudaFuncAttributeMaxDynamicSharedMemorySize, FPS_SMEM);
    cudaFuncSetAttribute(mlp_kernel, cudaFuncAttributeMaxDynamicSharedMemorySize, MLP_SMEM);

    pack_kernel<<<(N_PTS + 255) / 256, 256>>>(pos);
    mlp_kernel<<<N_PTS / 64, 256, MLP_SMEM>>>(x, W, b);
    fps_kernel<<<FPS_CTAS, FPS_T, FPS_SMEM>>>(out + (size_t)M_PTS * COUT);
    knn_kernel<<<dim3(M_PTS / 256, NCHUNK), 256>>>();
    merge_kernel<<<M_PTS / 256, 256>>>(batch, out);
    gather_max_kernel<<<M_PTS / 8, 256>>>(out);
}

// round 13
// speedup vs baseline: 1.1522x; 1.0340x over previous
#include <cuda_runtime.h>
#include <cstdint>
#include <cstddef>

// Problem constants (fixed by the dataset)
#define N_PTS 32768
#define M_PTS 8192          // N * 0.25
#define CIN   64
#define COUT  128
#define KK    16

// ---------------- FPS config ----------------
#define FPS_CTAS 8
#define FPS_T    512
#define PPC (N_PTS / FPS_CTAS)   // 4096 points per CTA
#define PPT (PPC / FPS_T)        // 8 points per thread
#define NPAIR (PPT / 2)          // 4 packed f32x2 pairs
#define NWARPS (FPS_T / 32)      // 16

// Consumer (overlapped KNN) config: grid = FPS_CTAS + NQT*NCHUNK = 136 blocks.
#define NCHUNK   8
#define CHUNK_PTS (N_PTS / NCHUNK)   // 4096
#define NQT      16                  // 16 query tiles of 512
#define QT_SZ    512
#define FPS_GRID (FPS_CTAS + NQT * NCHUNK)   // 136 (divisible by 8)

// FPS shared memory layout (bytes) — SM_POS doubles as the consumer KNN tile.
#define SM_POS   0                          // float4[4096] = 65536
#define SM_WRED  65536                      // u64[16]      = 128
#define SM_SLOT  65664                      // 2 parities x 8 ranks x 32B = 512
#define SM_WIN   66176                      // float[4] winner broadcast
#define FPS_SMEM 66304

#define XP 68                               // padded stride for MLP x-transpose tile
#define MLP_SMEM (64 * XP * 4 + CIN * COUT * 4)   // 17408 + 32768 = 50176

// Slot layout (32B): [0]=val_bits [4]=~idx [8]=x_bits [12]=y_bits
//                    [16]=flag(=round s) [20]=z_bits [24..31] pad
// (z,flag) written as ONE st.release.cluster.b64: seeing flag==s via
// ld.acquire.cluster guarantees the v4 payload is visible to that lane.
// NO cluster-scope fences anywhere in the loop (they emit CCTL.IVALL).

// ---------------- device scratch (no allocations allowed) ----------------
__device__ float4   g_pos4[N_PTS];
__device__ float4   g_sub4[M_PTS];
__device__ int      g_fps_idx[M_PTS];
__device__ unsigned g_progress;             // last FPS round published (released)
__device__ float4   g_h4[N_PTS * (COUT / 4)];               // 16 MB: relu(xW+b)
__device__ float    g_cand_d[(size_t)M_PTS * NCHUNK * KK];
__device__ int      g_cand_i[(size_t)M_PTS * NCHUNK * KK];
__device__ int      g_nbr[M_PTS * KK];

// ---------------- small PTX helpers ----------------
__device__ __forceinline__ unsigned s2u(const void* p) {
    return (unsigned)__cvta_generic_to_shared(p);
}
__device__ __forceinline__ unsigned mapa_rank(unsigned a, unsigned r) {
    unsigned ret;
    asm("mapa.shared::cluster.u32 %0, %1, %2;" : "=r"(ret) : "r"(a), "r"(r));
    return ret;
}
__device__ __forceinline__ void cluster_barrier() {
    asm volatile("barrier.cluster.arrive.aligned;" ::: "memory");
    asm volatile("barrier.cluster.wait.aligned;" ::: "memory");
}
__device__ __forceinline__ unsigned ctarank() {
    unsigned r;
    asm("mov.u32 %0, %%cluster_ctarank;" : "=r"(r));
    return r;
}
// Packed f32x2: two independent IEEE-rn fp32 lanes per op (bit-identical to
// the scalar rn sequence; verified rel_err==0.0 across prior rounds).
#define PK2(out, lo, hi) \
    asm("mov.b64 %0, {%1, %2};" : "=l"(out) : "r"(lo), "r"(hi))
#define UPK2(lo, hi, in) \
    asm("mov.b64 {%0, %1}, %2;" : "=r"(lo), "=r"(hi) : "l"(in))
#define ADD2(out, a, b) \
    asm("add.rn.f32x2 %0, %1, %2;" : "=l"(out) : "l"(a), "l"(b))
#define MUL2(out, a, b) \
    asm("mul.rn.f32x2 %0, %1, %2;" : "=l"(out) : "l"(a), "l"(b))

// ---------------- pack pos -> float4 (+ progress reset) ----------------
__global__ void pack_kernel(const float* __restrict__ pos) {
    int i = blockIdx.x * 256 + threadIdx.x;
    if (i == 0) g_progress = 0u;   // reset for this launch (graph replays!)
    if (i < N_PTS) {
        float4 v;
        v.x = pos[3 * i + 0];
        v.y = pos[3 * i + 1];
        v.z = pos[3 * i + 2];
        v.w = 0.0f;
        g_pos4[i] = v;
    }
}

// ---------------- FPS (cluster 0, R10 verbatim) + KNN consumers (clusters 1..16)
// FPS exactly replicates: for s: d = sum((pos-pos[last])**2); mind = min(mind,d);
//                         next = argmax(mind)  (first-occurrence tie-break)
// d = add(add(mul(dx,dx),mul(dy,dy)),mul(dz,dz)) in rn, dx = px + (-lx) [== px-lx].
// Tie-break: key = (val_bits<<32) | ~global_idx, max -> lowest global idx on ties.
// Progress protocol: rank0 winner lane writes g_sub4[s] (plain STG), then every
// 512th round st.release.gpu(g_progress = s). Consumers ld.acquire.gpu until
// progress >= qbase+511; hb chain (prior rounds' writes -> syncthreads ->
// release) makes all g_sub4[0..s] visible. 16 release stores total.
// Deadlock-free: 136 blocks <= wave-1 capacity (smem 66KB -> 3 CTA/SM, 444).
__global__ void __cluster_dims__(FPS_CTAS, 1, 1) fps_kernel(float* __restrict__ subpos_out) {
    extern __shared__ char smraw[];

    if (blockIdx.x >= FPS_CTAS) {
        // ================= KNN consumer block =================
        float4* tile = (float4*)(smraw + SM_POS);   // 4096 float4 = 64KB
        const int item  = blockIdx.x - FPS_CTAS;    // 0..127
        const int qt    = item & (NQT - 1);         // query tile
        const int chunk = item >> 4;                // point chunk
        const int tid   = threadIdx.x;
        const int q     = qt * QT_SZ + tid;
        const unsigned need = (unsigned)(qt * QT_SZ + (QT_SZ - 1));

        if (tid == 0) {
            unsigned p;
            do {
                asm volatile("ld.acquire.gpu.u32 %0, [%1];"
                             : "=r"(p) : "l"(&g_progress) : "memory");
                if (p < need) __nanosleep(256);
            } while (p < need);
        }
        __syncthreads();                 // progress acquire ordered for all

        const int base = chunk * CHUNK_PTS;
        for (int i = tid; i < CHUNK_PTS; i += QT_SZ)
            tile[i] = g_pos4[base + i];
        __syncthreads();

        float4 qp = g_sub4[q];
        float bd[KK];
        int   bi[KK];
        #pragma unroll
        for (int k = 0; k < KK; ++k) { bd[k] = __int_as_float(0x7f800000); bi[k] = 0; }

        for (int i = 0; i < CHUNK_PTS; ++i) {
            float4 p = tile[i];
            float dx = __fsub_rn(qp.x, p.x);
            float dy = __fsub_rn(qp.y, p.y);
            float dz = __fsub_rn(qp.z, p.z);
            float d  = __fadd_rn(__fadd_rn(__fmul_rn(dx, dx), __fmul_rn(dy, dy)),
                                 __fmul_rn(dz, dz));
            if (d < bd[KK - 1]) {       // strict <: stable (earlier index wins ties)
                bd[KK - 1] = d;
                bi[KK - 1] = base + i;
                #pragma unroll
                for (int j = KK - 1; j > 0; --j) {
                    if (bd[j] < bd[j - 1]) {
                        float td = bd[j]; bd[j] = bd[j - 1]; bd[j - 1] = td;
                        int   ti = bi[j]; bi[j] = bi[j - 1]; bi[j - 1] = ti;
                    }
                }
            }
        }
        size_t o = ((size_t)q * NCHUNK + chunk) * KK;
        #pragma unroll
        for (int k = 0; k < KK; ++k) {
            g_cand_d[o + k] = bd[k];
            g_cand_i[o + k] = bi[k];
        }
        return;
    }

    // ================= FPS (R10 verbatim + 3-instr progress publish) =========
    float4*             spos = (float4*)(smraw + SM_POS);
    unsigned long long* wred = (unsigned long long*)(smraw + SM_WRED);
    float*              swin = (float*)(smraw + SM_WIN);

    const unsigned rank = ctarank();
    const int tid  = threadIdx.x;
    const int lane = tid & 31;
    const int wid  = tid >> 5;
    const int gbase = (int)rank * PPC;

    // Init slot flags to a value no round uses (rounds are 1..M-1).
    if (tid < 16) {
        ((unsigned long long*)(smraw + SM_SLOT))[tid * 4 + 2] = 0xFFFFFFFFFFFFFFFFull;
    }

    // Load my slice into SMEM (winner-xyz lookup) and packed registers (compute).
    unsigned long long px2[NPAIR], py2[NPAIR], pz2[NPAIR];
    float md[PPT];
    #pragma unroll
    for (int i = 0; i < NPAIR; ++i) {
        float4 a = g_pos4[gbase + tid + (2 * i) * FPS_T];
        float4 b = g_pos4[gbase + tid + (2 * i + 1) * FPS_T];
        spos[tid + (2 * i) * FPS_T]     = a;
        spos[tid + (2 * i + 1) * FPS_T] = b;
        PK2(px2[i], __float_as_uint(a.x), __float_as_uint(b.x));
        PK2(py2[i], __float_as_uint(a.y), __float_as_uint(b.y));
        PK2(pz2[i], __float_as_uint(a.z), __float_as_uint(b.z));
        md[2 * i]     = __int_as_float(0x7f800000);   // +inf
        md[2 * i + 1] = __int_as_float(0x7f800000);
    }
    float4 p0 = g_pos4[0];
    if (rank == 0 && tid == 0) {
        g_fps_idx[0]  = 0;
        subpos_out[0] = p0.x;
        subpos_out[1] = p0.y;
        subpos_out[2] = p0.z;
        g_sub4[0] = make_float4(p0.x, p0.y, p0.z, 0.0f);
    }
    __syncthreads();
    cluster_barrier();   // all slot flags initialized before any remote store

    float lx = p0.x, ly = p0.y, lz = p0.z;

    for (int s = 1; s < M_PTS; ++s) {
        const int par = s & 1;
        // ---- packed min-dist update + per-thread argmax
        unsigned long long nlx2, nly2, nlz2;
        {
            unsigned nx = __float_as_uint(lx) ^ 0x80000000u;
            unsigned ny = __float_as_uint(ly) ^ 0x80000000u;
            unsigned nz = __float_as_uint(lz) ^ 0x80000000u;
            PK2(nlx2, nx, nx); PK2(nly2, ny, ny); PK2(nlz2, nz, nz);
        }
        float bv = -1.0f;
        int   bj = 0;
        #pragma unroll
        for (int i = 0; i < NPAIR; ++i) {
            unsigned long long dx2, dy2, dz2, xx2, yy2, zz2, s2, d2;
            ADD2(dx2, px2[i], nlx2);      // px - lx (exact: a + (-b))
            ADD2(dy2, py2[i], nly2);
            ADD2(dz2, pz2[i], nlz2);
            MUL2(xx2, dx2, dx2);
            MUL2(yy2, dy2, dy2);
            MUL2(zz2, dz2, dz2);
            ADD2(s2, xx2, yy2);
            ADD2(d2, s2, zz2);
            unsigned u0, u1;
            UPK2(u0, u1, d2);
            float m0 = fminf(md[2 * i], __uint_as_float(u0));
            md[2 * i] = m0;
            if (m0 > bv) { bv = m0; bj = 2 * i; }         // strict >, ascending j
            float m1 = fminf(md[2 * i + 1], __uint_as_float(u1));
            md[2 * i + 1] = m1;
            if (m1 > bv) { bv = m1; bj = 2 * i + 1; }
        }
        // ---- warp argmax via redux (bv >= 0 so uint order == float order)
        unsigned vb   = __float_as_uint(bv);
        unsigned wmax = __reduce_max_sync(0xFFFFFFFFu, vb);
        unsigned inv  = (vb == wmax) ? ~(unsigned)(gbase + tid + bj * FPS_T) : 0u;
        unsigned imax = __reduce_max_sync(0xFFFFFFFFu, inv);
        if (lane == 0)
            wred[wid] = ((unsigned long long)wmax << 32) | imax;
        __syncthreads();

        // ---- warp 0: block argmax, candidate broadcast, flag spin, winner pick
        if (wid == 0) {
            unsigned long long k = (lane < NWARPS) ? wred[lane] : 0ull;
            unsigned v2 = (unsigned)(k >> 32);
            unsigned m2 = __reduce_max_sync(0xFFFFFFFFu, v2);
            unsigned i2c = (v2 == m2) ? (unsigned)k : 0u;
            unsigned i2 = __reduce_max_sync(0xFFFFFFFFu, i2c);
            unsigned gi = ~i2;
            int li = (int)gi - gbase;
            float4 c = spos[li];              // broadcast LDS, all lanes same addr

            const char* sb = smraw + SM_SLOT + par * (FPS_CTAS * 32);
            unsigned long long mykey = 0;
            float sx = 0.f, sy = 0.f, sz = 0.f;
            if (lane < FPS_CTAS) {
                // post my CTA's candidate into slot[rank] of CTA 'lane'
                unsigned a = mapa_rank(s2u(sb + (int)rank * 32), (unsigned)lane);
                asm volatile("st.shared::cluster.v4.b32 [%0], {%1,%2,%3,%4};"
                             :: "r"(a), "r"(m2), "r"(i2),
                                "r"(__float_as_uint(c.x)), "r"(__float_as_uint(c.y))
                             : "memory");
                unsigned long long zf =
                    ((unsigned long long)__float_as_uint(c.z) << 32) | (unsigned)s;
                asm volatile("st.release.cluster.shared::cluster.b64 [%0], %1;"
                             :: "r"(a + 16), "l"(zf) : "memory");

                // spin on MY local flag (slot[lane]) until round s posted
                unsigned fa = s2u(sb + lane * 32 + 16);
                unsigned long long zfl;
                do {
                    asm volatile("ld.acquire.cluster.shared::cta.b64 %0, [%1];"
                                 : "=l"(zfl) : "r"(fa) : "memory");
                } while ((unsigned)zfl != (unsigned)s);
                uint4 v = *(const uint4*)(sb + lane * 32);  // ordered by my acquire
                mykey = ((unsigned long long)v.x << 32) | v.y;
                sx = __uint_as_float(v.z);
                sy = __uint_as_float(v.w);
                sz = __uint_as_float((unsigned)(zfl >> 32));
            }
            // winner across the 8 lane-held candidates
            unsigned v3 = (unsigned)(mykey >> 32);
            unsigned m3 = __reduce_max_sync(0xFFFFFFFFu, v3);
            unsigned i3c = (v3 == m3 && lane < FPS_CTAS) ? (unsigned)mykey : 0u;
            unsigned i3 = __reduce_max_sync(0xFFFFFFFFu, i3c);
            unsigned long long wkey = ((unsigned long long)m3 << 32) | i3;
            if (lane < FPS_CTAS && mykey == wkey) {
                swin[0] = sx;
                swin[1] = sy;
                swin[2] = sz;
                if (rank == 0) {
                    unsigned wg = ~i3;
                    g_fps_idx[s] = (int)wg;
                    subpos_out[3 * s + 0] = sx;
                    subpos_out[3 * s + 1] = sy;
                    subpos_out[3 * s + 2] = sz;
                    g_sub4[s] = make_float4(sx, sy, sz, 0.0f);
                    if ((s & 511) == 511) {   // publish progress (16x total)
                        asm volatile("st.release.gpu.u32 [%0], %1;"
                                     :: "l"(&g_progress), "r"((unsigned)s)
                                     : "memory");
                    }
                }
            }
        }
        __syncthreads();   // releases warps 1..15; orders swin for all
        lx = swin[0];
        ly = swin[1];
        lz = swin[2];
    }
}

// ---------------- MLP: h = relu(x @ W + b), fp32 ----------------
__global__ void mlp_kernel(const float* __restrict__ x,
                           const float* __restrict__ W,
                           const float* __restrict__ bias) {
    extern __shared__ float sm[];
    float* sX = sm;                 // [CIN][XP]  (k-major, padded)
    float* sW = sm + 64 * XP;       // [CIN][COUT]
    int rBase = blockIdx.x * 64;

    for (int i = threadIdx.x; i < (CIN * COUT) / 4; i += 256)
        ((float4*)sW)[i] = ((const float4*)W)[i];
    for (int i = threadIdx.x; i < 1024; i += 256) {
        int r  = i >> 4;
        int k4 = (i & 15) << 2;
        float4 v = ((const float4*)(x + (size_t)(rBase + r) * CIN))[i & 15];
        sX[(k4 + 0) * XP + r] = v.x;
        sX[(k4 + 1) * XP + r] = v.y;
        sX[(k4 + 2) * XP + r] = v.z;
        sX[(k4 + 3) * XP + r] = v.w;
    }
    __syncthreads();

    int ty = threadIdx.x >> 4, tx = threadIdx.x & 15;
    int r0 = ty * 4, c0 = tx * 8;
    float acc[4][8];
    #pragma unroll
    for (int i = 0; i < 4; ++i)
        #pragma unroll
        for (int j = 0; j < 8; ++j) acc[i][j] = 0.0f;

    #pragma unroll 4
    for (int k = 0; k < CIN; ++k) {
        float4 xr = *(const float4*)&sX[k * XP + r0];
        float4 wa = *(const float4*)&sW[k * COUT + c0];
        float4 wb = *(const float4*)&sW[k * COUT + c0 + 4];
        float xv[4] = {xr.x, xr.y, xr.z, xr.w};
        float wv[8] = {wa.x, wa.y, wa.z, wa.w, wb.x, wb.y, wb.z, wb.w};
        #pragma unroll
        for (int i = 0; i < 4; ++i)
            #pragma unroll
            for (int j = 0; j < 8; ++j)
                acc[i][j] = fmaf(xv[i], wv[j], acc[i][j]);
    }
    #pragma unroll
    for (int i = 0; i < 4; ++i) {
        int row = rBase + r0 + i;
        float4 o1, o2;
        o1.x = fmaxf(acc[i][0] + bias[c0 + 0], 0.0f);
        o1.y = fmaxf(acc[i][1] + bias[c0 + 1], 0.0f);
        o1.z = fmaxf(acc[i][2] + bias[c0 + 2], 0.0f);
        o1.w = fmaxf(acc[i][3] + bias[c0 + 3], 0.0f);
        o2.x = fmaxf(acc[i][4] + bias[c0 + 4], 0.0f);
        o2.y = fmaxf(acc[i][5] + bias[c0 + 5], 0.0f);
        o2.z = fmaxf(acc[i][6] + bias[c0 + 6], 0.0f);
        o2.w = fmaxf(acc[i][7] + bias[c0 + 7], 0.0f);
        g_h4[(size_t)row * (COUT / 4) + (c0 >> 2) + 0] = o1;
        g_h4[(size_t)row * (COUT / 4) + (c0 >> 2) + 1] = o2;
    }
}

// ---------------- KNN phase 2: merge 8 sorted lists + sub_batch ----------------
__global__ void merge_kernel(const int* __restrict__ batch, float* __restrict__ d_out) {
    int q = blockIdx.x * 256 + threadIdx.x;
    if (q >= M_PTS) return;
    int head[NCHUNK];
    unsigned long long hk[NCHUNK];
    #pragma unroll
    for (int c = 0; c < NCHUNK; ++c) {
        head[c] = 0;
        size_t o = ((size_t)q * NCHUNK + c) * KK;
        hk[c] = ((unsigned long long)__float_as_uint(g_cand_d[o]) << 32) |
                (unsigned)g_cand_i[o];
    }
    #pragma unroll
    for (int k = 0; k < KK; ++k) {
        int cb = 0;
        unsigned long long bk = hk[0];
        #pragma unroll
        for (int c = 1; c < NCHUNK; ++c)
            if (hk[c] < bk) { bk = hk[c]; cb = c; }
        g_nbr[q * KK + k] = (int)(bk & 0xFFFFFFFFull);
        int h = ++head[cb];
        if (h < KK) {
            size_t o = ((size_t)q * NCHUNK + cb) * KK + h;
            hk[cb] = ((unsigned long long)__float_as_uint(g_cand_d[o]) << 32) |
                     (unsigned)g_cand_i[o];
        } else {
            hk[cb] = 0xFFFFFFFFFFFFFFFFull;
        }
    }
    d_out[(size_t)M_PTS * COUT + (size_t)M_PTS * 3 + q] = (float)batch[g_fps_idx[q]];
}

// ---------------- gather + max over K neighbors ----------------
__global__ void gather_max_kernel(float* __restrict__ d_out) {
    int gw   = (blockIdx.x * blockDim.x + threadIdx.x) >> 5;   // query id
    int lane = threadIdx.x & 31;
    float4 acc = make_float4(-__int_as_float(0x7f800000),
                             -__int_as_float(0x7f800000),
                             -__int_as_float(0x7f800000),
                             -__int_as_float(0x7f800000));
    #pragma unroll
    for (int k = 0; k < KK; ++k) {
        int n = g_nbr[gw * KK + k];
        float4 v = g_h4[(size_t)n * (COUT / 4) + lane];
        acc.x = fmaxf(acc.x, v.x);
        acc.y = fmaxf(acc.y, v.y);
        acc.z = fmaxf(acc.z, v.z);
        acc.w = fmaxf(acc.w, v.w);
    }
    ((float4*)d_out)[(size_t)gw * (COUT / 4) + lane] = acc;
}

// ---------------- launch ----------------
extern "C" void kernel_launch(void* const* d_in, const int* in_sizes, int n_in,
                              void* d_out, int out_size) {
    const float* x     = (const float*)d_in[0];
    const float* pos   = (const float*)d_in[1];
    const int*   batch = (const int*)  d_in[2];
    const float* W     = (const float*)d_in[3];
    const float* b     = (const float*)d_in[4];
    float* out = (float*)d_out;
    (void)in_sizes; (void)n_in; (void)out_size;

    cudaFuncSetAttribute(fps_kernel, cudaFuncAttributeMaxDynamicSharedMemorySize, FPS_SMEM);
    cudaFuncSetAttribute(mlp_kernel, cudaFuncAttributeMaxDynamicSharedMemorySize, MLP_SMEM);

    pack_kernel<<<(N_PTS + 255) / 256, 256>>>(pos);
    mlp_kernel<<<N_PTS / 64, 256, MLP_SMEM>>>(x, W, b);
    fps_kernel<<<FPS_GRID, FPS_T, FPS_SMEM>>>(out + (size_t)M_PTS * COUT);
    merge_kernel<<<M_PTS / 256, 256>>>(batch, out);
    gather_max_kernel<<<M_PTS / 8, 256>>>(out);
}

// round 14
// speedup vs baseline: 1.3263x; 1.1511x over previous
#include <cuda_runtime.h>
#include <cstdint>
#include <cstddef>

// Problem constants (fixed by the dataset)
#define N_PTS 32768
#define M_PTS 8192          // N * 0.25
#define CIN   64
#define COUT  128
#define KK    16

// ---------------- FPS config ----------------
#define FPS_CTAS 8
#define FPS_T    512
#define PPC (N_PTS / FPS_CTAS)   // 4096 points per CTA
#define PPT (PPC / FPS_T)        // 8 points per thread
#define NPAIR (PPT / 2)          // 4 packed f32x2 pairs
#define NWARPS (FPS_T / 32)      // 16

// FPS shared memory layout (bytes)
#define SM_POS   0                          // float4[4096] = 65536
#define SM_WRED  65536                      // u64[16]      = 128
#define SM_SLOT  65664                      // 2 parities x 8 ranks x 32B = 512
#define SM_WIN   66176                      // float[4] winner broadcast
#define FPS_SMEM 66304

#define XP 68                               // padded stride for MLP x-transpose tile
#define MLP_SMEM (64 * XP * 4 + CIN * COUT * 4)   // 17408 + 32768 = 50176

#define NCHUNK   8
#define KNN_TILE 2048
#define KNN_TP   (KNN_TILE / 2)   // 1024 packed pairs per tile

// Slot layout (32B): [0]=val_bits [4]=~idx [8]=x_bits [12]=y_bits
//                    [16]=flag(=round s) [20]=z_bits [24..31] pad
// (z,flag) written as ONE st.release.cluster.b64: seeing flag==s via
// ld.acquire.cluster guarantees the v4 payload is visible to that lane.
// NO cluster-scope fences anywhere in the loop (they emit CCTL.IVALL).

// ---------------- device scratch (no allocations allowed) ----------------
__device__ float4 g_pos4[N_PTS];
__device__ float4 g_sub4[M_PTS];
__device__ int    g_fps_idx[M_PTS];
__device__ float4 g_h4[N_PTS * (COUT / 4)];                 // 16 MB: relu(xW+b)
__device__ float  g_cand_d[(size_t)M_PTS * NCHUNK * KK];
__device__ int    g_cand_i[(size_t)M_PTS * NCHUNK * KK];
__device__ int    g_nbr[M_PTS * KK];

// ---------------- small PTX helpers ----------------
__device__ __forceinline__ unsigned s2u(const void* p) {
    return (unsigned)__cvta_generic_to_shared(p);
}
__device__ __forceinline__ unsigned mapa_rank(unsigned a, unsigned r) {
    unsigned ret;
    asm("mapa.shared::cluster.u32 %0, %1, %2;" : "=r"(ret) : "r"(a), "r"(r));
    return ret;
}
__device__ __forceinline__ void cluster_barrier() {
    asm volatile("barrier.cluster.arrive.aligned;" ::: "memory");
    asm volatile("barrier.cluster.wait.aligned;" ::: "memory");
}
__device__ __forceinline__ unsigned ctarank() {
    unsigned r;
    asm("mov.u32 %0, %%cluster_ctarank;" : "=r"(r));
    return r;
}
// Packed f32x2: two independent IEEE-rn fp32 lanes per op (bit-identical to
// the scalar rn sequence; verified rel_err==0.0 across prior rounds).
#define PK2(out, lo, hi) \
    asm("mov.b64 %0, {%1, %2};" : "=l"(out) : "r"(lo), "r"(hi))
#define UPK2(lo, hi, in) \
    asm("mov.b64 {%0, %1}, %2;" : "=r"(lo), "=r"(hi) : "l"(in))
#define ADD2(out, a, b) \
    asm("add.rn.f32x2 %0, %1, %2;" : "=l"(out) : "l"(a), "l"(b))
#define MUL2(out, a, b) \
    asm("mul.rn.f32x2 %0, %1, %2;" : "=l"(out) : "l"(a), "l"(b))

// ---------------- pack pos -> float4 ----------------
__global__ void pack_kernel(const float* __restrict__ pos) {
    int i = blockIdx.x * 256 + threadIdx.x;
    if (i < N_PTS) {
        float4 v;
        v.x = pos[3 * i + 0];
        v.y = pos[3 * i + 1];
        v.z = pos[3 * i + 2];
        v.w = 0.0f;
        g_pos4[i] = v;
    }
}

// ---------------- FPS: 8-CTA cluster; packed f32x2 update; warp0 flag spin
// (R10 structure, byte-for-byte — FROZEN; 6 attempted variants all regressed).
// Exactly replicates:  for s: d = sum((pos-pos[last])**2); mind = min(mind,d);
//                      next = argmax(mind)  (first-occurrence tie-break)
// d = add(add(mul(dx,dx),mul(dy,dy)),mul(dz,dz)) in rn, dx = px + (-lx) [== px-lx].
// Tie-break: key = (val_bits<<32) | ~global_idx, max -> lowest global idx on ties.
__global__ void __cluster_dims__(FPS_CTAS, 1, 1) fps_kernel(float* __restrict__ subpos_out) {
    extern __shared__ char smraw[];
    float4*             spos = (float4*)(smraw + SM_POS);
    unsigned long long* wred = (unsigned long long*)(smraw + SM_WRED);
    float*              swin = (float*)(smraw + SM_WIN);

    const unsigned rank = ctarank();
    const int tid  = threadIdx.x;
    const int lane = tid & 31;
    const int wid  = tid >> 5;
    const int gbase = (int)rank * PPC;

    // Init slot flags to a value no round uses (rounds are 1..M-1).
    if (tid < 16) {
        ((unsigned long long*)(smraw + SM_SLOT))[tid * 4 + 2] = 0xFFFFFFFFFFFFFFFFull;
    }

    // Load my slice into SMEM (winner-xyz lookup) and packed registers (compute).
    // Pair i holds points j=2i (lo lane) and j=2i+1 (hi lane);
    // global idx of point j = gbase + tid + j*FPS_T (ascending in j).
    unsigned long long px2[NPAIR], py2[NPAIR], pz2[NPAIR];
    float md[PPT];
    #pragma unroll
    for (int i = 0; i < NPAIR; ++i) {
        float4 a = g_pos4[gbase + tid + (2 * i) * FPS_T];
        float4 b = g_pos4[gbase + tid + (2 * i + 1) * FPS_T];
        spos[tid + (2 * i) * FPS_T]     = a;
        spos[tid + (2 * i + 1) * FPS_T] = b;
        PK2(px2[i], __float_as_uint(a.x), __float_as_uint(b.x));
        PK2(py2[i], __float_as_uint(a.y), __float_as_uint(b.y));
        PK2(pz2[i], __float_as_uint(a.z), __float_as_uint(b.z));
        md[2 * i]     = __int_as_float(0x7f800000);   // +inf
        md[2 * i + 1] = __int_as_float(0x7f800000);
    }
    float4 p0 = g_pos4[0];
    if (rank == 0 && tid == 0) {
        g_fps_idx[0]  = 0;
        subpos_out[0] = p0.x;
        subpos_out[1] = p0.y;
        subpos_out[2] = p0.z;
        g_sub4[0] = make_float4(p0.x, p0.y, p0.z, 0.0f);
    }
    __syncthreads();
    cluster_barrier();   // all slot flags initialized before any remote store

    float lx = p0.x, ly = p0.y, lz = p0.z;

    for (int s = 1; s < M_PTS; ++s) {
        const int par = s & 1;
        // ---- packed min-dist update + per-thread argmax
        unsigned long long nlx2, nly2, nlz2;
        {
            unsigned nx = __float_as_uint(lx) ^ 0x80000000u;
            unsigned ny = __float_as_uint(ly) ^ 0x80000000u;
            unsigned nz = __float_as_uint(lz) ^ 0x80000000u;
            PK2(nlx2, nx, nx); PK2(nly2, ny, ny); PK2(nlz2, nz, nz);
        }
        float bv = -1.0f;
        int   bj = 0;
        #pragma unroll
        for (int i = 0; i < NPAIR; ++i) {
            unsigned long long dx2, dy2, dz2, xx2, yy2, zz2, s2, d2;
            ADD2(dx2, px2[i], nlx2);      // px - lx (exact: a + (-b))
            ADD2(dy2, py2[i], nly2);
            ADD2(dz2, pz2[i], nlz2);
            MUL2(xx2, dx2, dx2);
            MUL2(yy2, dy2, dy2);
            MUL2(zz2, dz2, dz2);
            ADD2(s2, xx2, yy2);
            ADD2(d2, s2, zz2);
            unsigned u0, u1;
            UPK2(u0, u1, d2);
            float m0 = fminf(md[2 * i], __uint_as_float(u0));
            md[2 * i] = m0;
            if (m0 > bv) { bv = m0; bj = 2 * i; }         // strict >, ascending j
            float m1 = fminf(md[2 * i + 1], __uint_as_float(u1));
            md[2 * i + 1] = m1;
            if (m1 > bv) { bv = m1; bj = 2 * i + 1; }
        }
        // ---- warp argmax via redux (bv >= 0 so uint order == float order)
        unsigned vb   = __float_as_uint(bv);
        unsigned wmax = __reduce_max_sync(0xFFFFFFFFu, vb);
        unsigned inv  = (vb == wmax) ? ~(unsigned)(gbase + tid + bj * FPS_T) : 0u;
        unsigned imax = __reduce_max_sync(0xFFFFFFFFu, inv);
        if (lane == 0)
            wred[wid] = ((unsigned long long)wmax << 32) | imax;
        __syncthreads();

        // ---- warp 0: block argmax, candidate broadcast, flag spin, winner pick
        if (wid == 0) {
            unsigned long long k = (lane < NWARPS) ? wred[lane] : 0ull;
            unsigned v2 = (unsigned)(k >> 32);
            unsigned m2 = __reduce_max_sync(0xFFFFFFFFu, v2);
            unsigned i2c = (v2 == m2) ? (unsigned)k : 0u;
            unsigned i2 = __reduce_max_sync(0xFFFFFFFFu, i2c);
            unsigned gi = ~i2;
            int li = (int)gi - gbase;
            float4 c = spos[li];              // broadcast LDS, all lanes same addr

            const char* sb = smraw + SM_SLOT + par * (FPS_CTAS * 32);
            unsigned long long mykey = 0;
            float sx = 0.f, sy = 0.f, sz = 0.f;
            if (lane < FPS_CTAS) {
                // post my CTA's candidate into slot[rank] of CTA 'lane'
                unsigned a = mapa_rank(s2u(sb + (int)rank * 32), (unsigned)lane);
                asm volatile("st.shared::cluster.v4.b32 [%0], {%1,%2,%3,%4};"
                             :: "r"(a), "r"(m2), "r"(i2),
                                "r"(__float_as_uint(c.x)), "r"(__float_as_uint(c.y))
                             : "memory");
                unsigned long long zf =
                    ((unsigned long long)__float_as_uint(c.z) << 32) | (unsigned)s;
                asm volatile("st.release.cluster.shared::cluster.b64 [%0], %1;"
                             :: "r"(a + 16), "l"(zf) : "memory");

                // spin on MY local flag (slot[lane]) until round s posted
                unsigned fa = s2u(sb + lane * 32 + 16);
                unsigned long long zfl;
                do {
                    asm volatile("ld.acquire.cluster.shared::cta.b64 %0, [%1];"
                                 : "=l"(zfl) : "r"(fa) : "memory");
                } while ((unsigned)zfl != (unsigned)s);
                uint4 v = *(const uint4*)(sb + lane * 32);  // ordered by my acquire
                mykey = ((unsigned long long)v.x << 32) | v.y;
                sx = __uint_as_float(v.z);
                sy = __uint_as_float(v.w);
                sz = __uint_as_float((unsigned)(zfl >> 32));
            }
            // winner across the 8 lane-held candidates
            unsigned v3 = (unsigned)(mykey >> 32);
            unsigned m3 = __reduce_max_sync(0xFFFFFFFFu, v3);
            unsigned i3c = (v3 == m3 && lane < FPS_CTAS) ? (unsigned)mykey : 0u;
            unsigned i3 = __reduce_max_sync(0xFFFFFFFFu, i3c);
            unsigned long long wkey = ((unsigned long long)m3 << 32) | i3;
            if (lane < FPS_CTAS && mykey == wkey) {
                swin[0] = sx;
                swin[1] = sy;
                swin[2] = sz;
                if (rank == 0) {
                    unsigned wg = ~i3;
                    g_fps_idx[s] = (int)wg;
                    subpos_out[3 * s + 0] = sx;
                    subpos_out[3 * s + 1] = sy;
                    subpos_out[3 * s + 2] = sz;
                    g_sub4[s] = make_float4(sx, sy, sz, 0.0f);
                }
            }
        }
        __syncthreads();   // releases warps 1..15; orders swin for all
        lx = swin[0];
        ly = swin[1];
        lz = swin[2];
    }
}

// ---------------- MLP: h = relu(x @ W + b), fp32 ----------------
__global__ void mlp_kernel(const float* __restrict__ x,
                           const float* __restrict__ W,
                           const float* __restrict__ bias) {
    extern __shared__ float sm[];
    float* sX = sm;                 // [CIN][XP]  (k-major, padded)
    float* sW = sm + 64 * XP;       // [CIN][COUT]
    int rBase = blockIdx.x * 64;

    for (int i = threadIdx.x; i < (CIN * COUT) / 4; i += 256)
        ((float4*)sW)[i] = ((const float4*)W)[i];
    for (int i = threadIdx.x; i < 1024; i += 256) {
        int r  = i >> 4;
        int k4 = (i & 15) << 2;
        float4 v = ((const float4*)(x + (size_t)(rBase + r) * CIN))[i & 15];
        sX[(k4 + 0) * XP + r] = v.x;
        sX[(k4 + 1) * XP + r] = v.y;
        sX[(k4 + 2) * XP + r] = v.z;
        sX[(k4 + 3) * XP + r] = v.w;
    }
    __syncthreads();

    int ty = threadIdx.x >> 4, tx = threadIdx.x & 15;
    int r0 = ty * 4, c0 = tx * 8;
    float acc[4][8];
    #pragma unroll
    for (int i = 0; i < 4; ++i)
        #pragma unroll
        for (int j = 0; j < 8; ++j) acc[i][j] = 0.0f;

    #pragma unroll 4
    for (int k = 0; k < CIN; ++k) {
        float4 xr = *(const float4*)&sX[k * XP + r0];
        float4 wa = *(const float4*)&sW[k * COUT + c0];
        float4 wb = *(const float4*)&sW[k * COUT + c0 + 4];
        float xv[4] = {xr.x, xr.y, xr.z, xr.w};
        float wv[8] = {wa.x, wa.y, wa.z, wa.w, wb.x, wb.y, wb.z, wb.w};
        #pragma unroll
        for (int i = 0; i < 4; ++i)
            #pragma unroll
            for (int j = 0; j < 8; ++j)
                acc[i][j] = fmaf(xv[i], wv[j], acc[i][j]);
    }
    #pragma unroll
    for (int i = 0; i < 4; ++i) {
        int row = rBase + r0 + i;
        float4 o1, o2;
        o1.x = fmaxf(acc[i][0] + bias[c0 + 0], 0.0f);
        o1.y = fmaxf(acc[i][1] + bias[c0 + 1], 0.0f);
        o1.z = fmaxf(acc[i][2] + bias[c0 + 2], 0.0f);
        o1.w = fmaxf(acc[i][3] + bias[c0 + 3], 0.0f);
        o2.x = fmaxf(acc[i][4] + bias[c0 + 4], 0.0f);
        o2.y = fmaxf(acc[i][5] + bias[c0 + 5], 0.0f);
        o2.z = fmaxf(acc[i][6] + bias[c0 + 6], 0.0f);
        o2.w = fmaxf(acc[i][7] + bias[c0 + 7], 0.0f);
        g_h4[(size_t)row * (COUT / 4) + (c0 >> 2) + 0] = o1;
        g_h4[(size_t)row * (COUT / 4) + (c0 >> 2) + 1] = o2;
    }
}

// ---------------- KNN phase 1: per-(query,chunk) top-16, f32x2-packed tile ----
// SoA-packed SMEM tile: pair p = points (2p, 2p+1). Per pair: 3x LDS.64 +
// 8 packed rn ops + 1 unpack + 2 scalar compares. Lane arithmetic identical to
// the scalar rn sequence ((q-p)^2 per lane); pair order 2p then 2p+1 preserves
// ascending-index insertion -> bit-identical stable top-16.
__global__ void knn_kernel() {
    __shared__ unsigned long long tx2[KNN_TP];
    __shared__ unsigned long long ty2[KNN_TP];
    __shared__ unsigned long long tz2[KNN_TP];
    int q     = blockIdx.x * 256 + threadIdx.x;    // 0..M-1
    int chunk = blockIdx.y;
    int base  = chunk * (N_PTS / NCHUNK);

    float4 qp = g_sub4[q];
    unsigned long long nqx2, nqy2, nqz2;           // packed (-qx,-qx) etc.
    {
        unsigned nx = __float_as_uint(qp.x) ^ 0x80000000u;
        unsigned ny = __float_as_uint(qp.y) ^ 0x80000000u;
        unsigned nz = __float_as_uint(qp.z) ^ 0x80000000u;
        PK2(nqx2, nx, nx); PK2(nqy2, ny, ny); PK2(nqz2, nz, nz);
    }

    float bd[KK];
    int   bi[KK];
    #pragma unroll
    for (int k = 0; k < KK; ++k) { bd[k] = __int_as_float(0x7f800000); bi[k] = 0; }

    for (int t = 0; t < (N_PTS / NCHUNK) / KNN_TILE; ++t) {
        int nb = base + t * KNN_TILE;
        for (int i = threadIdx.x; i < KNN_TP; i += 256) {
            float4 a = g_pos4[nb + 2 * i];
            float4 b = g_pos4[nb + 2 * i + 1];
            unsigned long long vx, vy, vz;
            PK2(vx, __float_as_uint(a.x), __float_as_uint(b.x));
            PK2(vy, __float_as_uint(a.y), __float_as_uint(b.y));
            PK2(vz, __float_as_uint(a.z), __float_as_uint(b.z));
            tx2[i] = vx; ty2[i] = vy; tz2[i] = vz;
        }
        __syncthreads();
        for (int i = 0; i < KNN_TP; ++i) {
            unsigned long long dx2, dy2, dz2, xx2, yy2, zz2, s2, d2;
            ADD2(dx2, tx2[i], nqx2);      // p - q (exact; square == (q-p)^2)
            ADD2(dy2, ty2[i], nqy2);
            ADD2(dz2, tz2[i], nqz2);
            MUL2(xx2, dx2, dx2);
            MUL2(yy2, dy2, dy2);
            MUL2(zz2, dz2, dz2);
            ADD2(s2, xx2, yy2);
            ADD2(d2, s2, zz2);
            unsigned u0, u1;
            UPK2(u0, u1, d2);
            float d0 = __uint_as_float(u0);
            if (d0 < bd[KK - 1]) {        // strict <: earlier index wins ties
                bd[KK - 1] = d0;
                bi[KK - 1] = nb + 2 * i;
                #pragma unroll
                for (int j = KK - 1; j > 0; --j) {
                    if (bd[j] < bd[j - 1]) {
                        float td = bd[j]; bd[j] = bd[j - 1]; bd[j - 1] = td;
                        int   ti = bi[j]; bi[j] = bi[j - 1]; bi[j - 1] = ti;
                    }
                }
            }
            float d1 = __uint_as_float(u1);
            if (d1 < bd[KK - 1]) {
                bd[KK - 1] = d1;
                bi[KK - 1] = nb + 2 * i + 1;
                #pragma unroll
                for (int j = KK - 1; j > 0; --j) {
                    if (bd[j] < bd[j - 1]) {
                        float td = bd[j]; bd[j] = bd[j - 1]; bd[j - 1] = td;
                        int   ti = bi[j]; bi[j] = bi[j - 1]; bi[j - 1] = ti;
                    }
                }
            }
        }
        __syncthreads();
    }
    size_t o = ((size_t)q * NCHUNK + chunk) * KK;
    #pragma unroll
    for (int k = 0; k < KK; ++k) {
        g_cand_d[o + k] = bd[k];
        g_cand_i[o + k] = bi[k];
    }
}

// ---------------- KNN phase 2: merge 8 sorted lists + sub_batch ----------------
__global__ void merge_kernel(const int* __restrict__ batch, float* __restrict__ d_out) {
    int q = blockIdx.x * 256 + threadIdx.x;
    if (q >= M_PTS) return;
    int head[NCHUNK];
    unsigned long long hk[NCHUNK];
    #pragma unroll
    for (int c = 0; c < NCHUNK; ++c) {
        head[c] = 0;
        size_t o = ((size_t)q * NCHUNK + c) * KK;
        hk[c] = ((unsigned long long)__float_as_uint(g_cand_d[o]) << 32) |
                (unsigned)g_cand_i[o];
    }
    #pragma unroll
    for (int k = 0; k < KK; ++k) {
        int cb = 0;
        unsigned long long bk = hk[0];
        #pragma unroll
        for (int c = 1; c < NCHUNK; ++c)
            if (hk[c] < bk) { bk = hk[c]; cb = c; }
        g_nbr[q * KK + k] = (int)(bk & 0xFFFFFFFFull);
        int h = ++head[cb];
        if (h < KK) {
            size_t o = ((size_t)q * NCHUNK + cb) * KK + h;
            hk[cb] = ((unsigned long long)__float_as_uint(g_cand_d[o]) << 32) |
                     (unsigned)g_cand_i[o];
        } else {
            hk[cb] = 0xFFFFFFFFFFFFFFFFull;
        }
    }
    d_out[(size_t)M_PTS * COUT + (size_t)M_PTS * 3 + q] = (float)batch[g_fps_idx[q]];
}

// ---------------- gather + max over K neighbors ----------------
__global__ void gather_max_kernel(float* __restrict__ d_out) {
    int gw   = (blockIdx.x * blockDim.x + threadIdx.x) >> 5;   // query id
    int lane = threadIdx.x & 31;
    float4 acc = make_float4(-__int_as_float(0x7f800000),
                             -__int_as_float(0x7f800000),
                             -__int_as_float(0x7f800000),
                             -__int_as_float(0x7f800000));
    #pragma unroll
    for (int k = 0; k < KK; ++k) {
        int n = g_nbr[gw * KK + k];
        float4 v = g_h4[(size_t)n * (COUT / 4) + lane];
        acc.x = fmaxf(acc.x, v.x);
        acc.y = fmaxf(acc.y, v.y);
        acc.z = fmaxf(acc.z, v.z);
        acc.w = fmaxf(acc.w, v.w);
    }
    ((float4*)d_out)[(size_t)gw * (COUT / 4) + lane] = acc;
}

// ---------------- launch ----------------
extern "C" void kernel_launch(void* const* d_in, const int* in_sizes, int n_in,
                              void* d_out, int out_size) {
    const float* x     = (const float*)d_in[0];
    const float* pos   = (const float*)d_in[1];
    const int*   batch = (const int*)  d_in[2];
    const float* W     = (const float*)d_in[3];
    const float* b     = (const float*)d_in[4];
    float* out = (float*)d_out;
    (void)in_sizes; (void)n_in; (void)out_size;

    cudaFuncSetAttribute(fps_kernel, cudaFuncAttributeMaxDynamicSharedMemorySize, FPS_SMEM);
    cudaFuncSetAttribute(mlp_kernel, cudaFuncAttributeMaxDynamicSharedMemorySize, MLP_SMEM);

    pack_kernel<<<(N_PTS + 255) / 256, 256>>>(pos);
    mlp_kernel<<<N_PTS / 64, 256, MLP_SMEM>>>(x, W, b);
    fps_kernel<<<FPS_CTAS, FPS_T, FPS_SMEM>>>(out + (size_t)M_PTS * COUT);
    knn_kernel<<<dim3(M_PTS / 256, NCHUNK), 256>>>();
    merge_kernel<<<M_PTS / 256, 256>>>(batch, out);
    gather_max_kernel<<<M_PTS / 8, 256>>>(out);
}